// round 14
// baseline (speedup 1.0000x reference)
#include <cuda_runtime.h>

#define T_STEPS 2048
#define BATCH   2048
#define HID     32
#define NPAIR   7          // warp pairs per CTA
#define NTHD    448        // 14 warps

typedef unsigned long long u64;

#define S_SIG  (-1.4426950408889634f)   /* -log2(e)   */
#define S_TNH  (-2.8853900817779268f)   /* -2*log2(e) */

// ---- packed f32x2 helpers ----
__device__ __forceinline__ u64 ffma2(u64 a, u64 b, u64 c) {
    u64 d;
    asm("fma.rn.f32x2 %0, %1, %2, %3;" : "=l"(d) : "l"(a), "l"(b), "l"(c));
    return d;
}
__device__ __forceinline__ u64 fadd2(u64 a, u64 b) {
    u64 d;
    asm("add.rn.f32x2 %0, %1, %2;" : "=l"(d) : "l"(a), "l"(b));
    return d;
}
__device__ __forceinline__ u64 pack2(float lo, float hi) {
    u64 d;
    asm("mov.b64 %0, {%1, %2};" : "=l"(d) : "f"(lo), "f"(hi));
    return d;
}
__device__ __forceinline__ void unpack2(u64 v, float& lo, float& hi) {
    asm("mov.b64 {%0, %1}, %2;" : "=f"(lo), "=f"(hi) : "l"(v));
}
__device__ __forceinline__ float ex2f(float x) {
    float y; asm("ex2.approx.f32 %0, %1;" : "=f"(y) : "f"(x)); return y;
}
__device__ __forceinline__ float rcpf(float x) {
    float y; asm("rcp.approx.f32 %0, %1;" : "=f"(y) : "f"(x)); return y;
}
__device__ __forceinline__ void stg32_pred(int pred, float* p, float a) {
    asm volatile("{\n\t"
                 ".reg .pred p;\n\t"
                 "setp.ne.u32 p, %0, 0;\n\t"
                 "@p st.global.f32 [%1], %2;\n\t"
                 "}" :: "r"(pred), "l"(p), "f"(a) : "memory");
}
__device__ __forceinline__ void pair_bar(int pair) {
    asm volatile("bar.sync %0, %1;" :: "r"(1 + pair), "r"(64) : "memory");
}

__global__ void __launch_bounds__(NTHD, 1) lstm_kernel(
    const float* __restrict__ x,      // [T, B, 1]
    const float* __restrict__ W_ih,   // [4H, 1]
    const float* __restrict__ W_hh,   // [4H, H]
    const float* __restrict__ b_ih,   // [4H]
    const float* __restrict__ b_hh,   // [4H]
    const float* __restrict__ W_out,  // [1, H]
    const float* __restrict__ b_out,  // [1]
    float* __restrict__ out,          // [T*B] outs, then [B*H] hT, then [B*H] cT
    int out_size)
{
    const int lane = threadIdx.x & 31;
    const int wid  = threadIdx.x >> 5;
    const int wip  = wid & 1;               // 0: k=0..15, acts b0; 1: k=16..31, acts b1
    const int pair = wid >> 1;              // 0..6
    const int gpair = blockIdx.x * NPAIR + pair;   // 0..1035
    const int valid = (gpair < BATCH / 2);
    const int b0 = valid ? 2 * gpair : (BATCH - 2);
    const int bg = b0 + wip;                // batch this warp activates

    // Own k-half of weight rows, pre-scaled (i,f,o: S_SIG; g: S_TNH): 32 u64.
    u64 w2[4][8];
    float wih[4], bias[4];
    #pragma unroll
    for (int g = 0; g < 4; g++) {
        const int row = g * 32 + lane;
        const float s = (g == 2) ? S_TNH : S_SIG;
        const float* wr = W_hh + row * HID + wip * 16;
        #pragma unroll
        for (int p = 0; p < 8; p++)
            w2[g][p] = pack2(wr[2 * p] * s, wr[2 * p + 1] * s);
        // only the k-lo warp injects x/bias (so partials sum to exactly one bias)
        wih[g]  = (wip == 0) ? (W_ih[row] * s) : 0.f;
        bias[g] = (wip == 0) ? ((b_ih[row] + b_hh[row]) * s) : 0.f;
    }
    const float wout = W_out[lane];
    const float bout = b_out[0];

    // smem: h per pair (double-buffered), exchange slots for partial gate sums
    __shared__ __align__(16) float shh[NPAIR][2][2][32];
    __shared__ __align__(16) u64  shex[NPAIR][2][4][32];

    // h(-1) = 0 for my batch
    shh[pair][0][wip][lane] = 0.f;
    __syncthreads();

    float h = 0.f, c = 0.f, rp = 0.f;       // state of my batch + deferred partial

    const float* xp = x + b0;
    float2 xv = *reinterpret_cast<const float2*>(xp);   // only used by wip==0 (wih=0 else)
    if (wip) { xv.x = 0.f; xv.y = 0.f; }
    float* outp = out + bg;
    const int store_pred = (lane == 0) && valid;

    #pragma unroll 2
    for (int t = 0; t < T_STEPS; t++) {
        const int buf = t & 1;

        // init partials: accM = my act-batch, accP = partner's act-batch
        u64 accM[4], accP[4];
        #pragma unroll
        for (int g = 0; g < 4; g++) {
            accM[g] = pack2(fmaf(xv.x, wih[g], bias[g]), 0.f);   // b_wip  (wip0: x.x; wip1: 0)
            accP[g] = pack2(fmaf(xv.y, wih[g], bias[g]), 0.f);   // b_1-wip(wip0: x.y; wip1: 0)
        }
        // NOTE for wip==1: accM is b1 (its x/bias comes from partner), accP is b0.
        // For wip==0: accM=b0 gets x.x, accP=b1 gets x.y.  For wip==1 both init 0. OK:
        // wip==1's accM(b1) pure k-sum; partner's accP(b1) carries bias+x.y.  Sum = exact.

        // deferred reduction of step t-1 output partial (hidden under matvec)
        float r = rp;
        #pragma unroll
        for (int off = 16; off; off >>= 1)
            r += __shfl_xor_sync(0xffffffffu, r, off);

        // matvec over own k-half for both batches (64 FFMA2)
        {
            const double2* hpM = reinterpret_cast<const double2*>(&shh[pair][buf][wip][wip * 16]);
            const double2* hpP = reinterpret_cast<const double2*>(&shh[pair][buf][wip ^ 1][wip * 16]);
            #pragma unroll
            for (int q = 0; q < 4; q++) {
                double2 vM = hpM[q], vP = hpP[q];
                u64 m0 = __double_as_longlong(vM.x), m1 = __double_as_longlong(vM.y);
                u64 p0 = __double_as_longlong(vP.x), p1 = __double_as_longlong(vP.y);
                #pragma unroll
                for (int g = 0; g < 4; g++) {
                    accM[g] = ffma2(m0, w2[g][2 * q],     accM[g]);
                    accP[g] = ffma2(p0, w2[g][2 * q],     accP[g]);
                }
                #pragma unroll
                for (int g = 0; g < 4; g++) {
                    accM[g] = ffma2(m1, w2[g][2 * q + 1], accM[g]);
                    accP[g] = ffma2(p1, w2[g][2 * q + 1], accP[g]);
                }
            }
        }

        // store out[t-1] for my batch (placeholder at t==0, overwritten at t==1)
        stg32_pred(store_pred, outp, r + bout);
        outp += (t > 0) ? BATCH : 0;

        // publish partner-batch partials; swap
        #pragma unroll
        for (int g = 0; g < 4; g++)
            shex[pair][wip][g][lane] = accP[g];
        pair_bar(pair);

        // combine: my batch = my half + partner's half
        float v[4];
        #pragma unroll
        for (int g = 0; g < 4; g++) {
            u64 full = fadd2(accM[g], shex[pair][wip ^ 1][g][lane]);
            float lo, hi;
            unpack2(full, lo, hi);
            v[g] = lo + hi;
        }

        // prefetch x(t+1)
        const float* xpn = (t < T_STEPS - 1) ? (xp + BATCH) : xp;
        float2 xnext = *reinterpret_cast<const float2*>(xpn);
        if (wip) { xnext.x = 0.f; xnext.y = 0.f; }
        xp = xpn;

        // activations (quad-shared rcp), single batch
        {
            float Ei = ex2f(v[0]), Ef = ex2f(v[1]), Eg = ex2f(v[2]), Eo = ex2f(v[3]);
            float Pi = 1.f + Ei, Pf = 1.f + Ef, Pg = 1.f + Eg, Po = 1.f + Eo;
            float Pif = Pi * Pf, Pgo = Pg * Po;
            float R = rcpf(Pif * Pgo);
            float PgoR = Pgo * R, PifR = Pif * R;
            float ig = Pf * PgoR;
            float fg = Pi * PgoR;
            float og = PifR * Pg;
            float gg = fmaf(2.f, PifR * Po, -1.f);
            c = fmaf(fg, c, ig * gg);
            float a = fminf(c * S_TNH, 63.f);
            float T = 1.f + ex2f(a);
            h = og * fmaf(2.f, rcpf(T), -1.f);
        }

        // publish h for next step, then barrier so partner's matvec sees it
        shh[pair][buf ^ 1][wip][lane] = h;
        rp = h * wout;
        xv = xnext;

        pair_bar(pair);
    }

    // epilogue: reduce final step partial -> out[T-1] (outp already at row T-1)
    {
        float r = rp;
        #pragma unroll
        for (int off = 16; off; off >>= 1)
            r += __shfl_xor_sync(0xffffffffu, r, off);
        stg32_pred(store_pred, outp, r + bout);
    }

    // final state (hT, cT) for my batch
    if (valid && out_size >= T_STEPS * BATCH + 2 * BATCH * HID) {
        float* hT = out + (size_t)T_STEPS * BATCH;
        float* cT = hT + BATCH * HID;
        hT[(size_t)bg * HID + lane] = h;
        cT[(size_t)bg * HID + lane] = c;
    }
}

extern "C" void kernel_launch(void* const* d_in, const int* in_sizes, int n_in,
                              void* d_out, int out_size) {
    const float* x     = (const float*)d_in[0];
    const float* W_ih  = (const float*)d_in[1];
    const float* W_hh  = (const float*)d_in[2];
    const float* b_ih  = (const float*)d_in[3];
    const float* b_hh  = (const float*)d_in[4];
    const float* W_out = (const float*)d_in[5];
    const float* b_out = (const float*)d_in[6];
    float* out = (float*)d_out;

    // 148 CTAs x 448 threads = 14 warps = 7 k-split pairs/CTA; 1036 pairs cover
    // 1024 batch-pairs in ONE wave on all 148 SMs, 3.5 warps/SMSP.
    lstm_kernel<<<148, NTHD>>>(x, W_ih, W_hh, b_ih, b_hh, W_out, b_out, out, out_size);
}